// round 1
// baseline (speedup 1.0000x reference)
#include <cuda_runtime.h>
#include <cuda_bf16.h>

#define GS 32
#define NN 16
#define ATOM_TYPE 6

// out[b,a,i,j,k] = sum_{n: an[a,n]==6} exp(coeff*((ti-dx)^2+(tj-dy)^2+(tk-dz)^2))
// Separable: ex[i]*ey[j]*ez[k]. Block = (ba, i-quarter). 256 threads.
// Thread t owns j = t>>3, k0 = (t&7)*4 -> one float4 per i-slice.
__global__ __launch_bounds__(256, 4) void voxel_kernel(
    const float* __restrict__ dv,     // (B, A, N, 3)
    const int*   __restrict__ an,     // (A, N) int32
    const float* __restrict__ sigma,  // (1,)
    float* __restrict__ out)          // (B, A, G, G, G)
{
    const int ba = blockIdx.x;   // b*32 + a
    const int a  = ba & 31;
    const int iq = blockIdx.y;   // i in [iq*8, iq*8+8)
    const int t  = threadIdx.x;
    const int j  = t >> 3;
    const int k0 = (t & 7) << 2;

    __shared__ float s_exi[NN][8];
    __shared__ float s_ey[NN][GS];
    __shared__ __align__(16) float s_ez[NN][GS];
    __shared__ float s_dx[NN], s_dy[NN], s_dz[NN];
    __shared__ int   s_act[NN];
    __shared__ int   s_nact;

    // Compact active-neighbor list (tiny; one thread)
    if (t == 0) {
        int c = 0;
        #pragma unroll
        for (int n = 0; n < NN; ++n)
            if (an[a * NN + n] == ATOM_TYPE) s_act[c++] = n;
        s_nact = c;
    }
    __syncthreads();
    const int nact = s_nact;

    const float sg = sigma[0];
    const float coeff = -0.5f / (sg * sg);
    const float step = 8.0f / 31.0f;

    // Load displacement vectors for active neighbors
    if (t < nact) {
        const int n = s_act[t];
        const float* p = dv + ((long)ba * NN + n) * 3;
        s_dx[t] = p[0];
        s_dy[t] = p[1];
        s_dz[t] = p[2];
    }
    __syncthreads();

    // Precompute separable exponential factors into shared memory
    for (int idx = t; idx < nact * GS; idx += 256) {
        const int m = idx >> 5, g = idx & 31;
        const float tick = -4.0f + (float)g * step;
        const float dyv = tick - s_dy[m];
        const float dzv = tick - s_dz[m];
        s_ey[m][g] = __expf(coeff * dyv * dyv);
        s_ez[m][g] = __expf(coeff * dzv * dzv);
    }
    for (int idx = t; idx < nact * 8; idx += 256) {
        const int m = idx >> 3, ii = idx & 7;
        const float tick = -4.0f + (float)(iq * 8 + ii) * step;
        const float dxv = tick - s_dx[m];
        s_exi[m][ii] = __expf(coeff * dxv * dxv);
    }
    __syncthreads();

    // Each thread accumulates 4 outputs per i-slice; float4 coalesced stores.
    float* outp = out + (long)ba * (GS * GS * GS)
                      + (long)iq * 8 * (GS * GS)
                      + 4 * t;   // j*32 + k0 == 4*t

    #pragma unroll
    for (int ii = 0; ii < 8; ++ii) {
        float4 acc = make_float4(0.f, 0.f, 0.f, 0.f);
        for (int m = 0; m < nact; ++m) {
            const float f = s_exi[m][ii] * s_ey[m][j];         // broadcast LDS
            const float4 ez4 = *reinterpret_cast<const float4*>(&s_ez[m][k0]);
            acc.x = fmaf(f, ez4.x, acc.x);
            acc.y = fmaf(f, ez4.y, acc.y);
            acc.z = fmaf(f, ez4.z, acc.z);
            acc.w = fmaf(f, ez4.w, acc.w);
        }
        *reinterpret_cast<float4*>(outp + ii * (GS * GS)) = acc;
    }
}

extern "C" void kernel_launch(void* const* d_in, const int* in_sizes, int n_in,
                              void* d_out, int out_size) {
    const float* dv    = (const float*)d_in[0];   // distance_vector (B,32,16,3)
    const int*   an    = (const int*)d_in[1];     // atomic_numbers (32,16) int32
    const float* sigma = (const float*)d_in[2];   // (1,)
    float* out = (float*)d_out;

    const int B = in_sizes[0] / (32 * 16 * 3);    // derive batch from input size
    dim3 grid(B * 32, 4);
    voxel_kernel<<<grid, 256>>>(dv, an, sigma, out);
}